// round 3
// baseline (speedup 1.0000x reference)
#include <cuda_runtime.h>
#include <cstdint>

#define CDIV(a,b) (((a)+(b)-1)/(b))

static constexpr int T_TOK = 8192;
static constexpr int DM    = 1024;
static constexpr int DFF   = 4096;
static constexpr int NE    = 8;
static constexpr int TOPK  = 2;
static constexpr int SLOTS = T_TOK * TOPK;      // 16384 routed slots

static constexpr int TM     = 128;              // CTA M tile
static constexpr int TN     = 256;              // CTA N tile
static constexpr int KC     = 32;               // K floats per stage
static constexpr int STAGES = 4;
static constexpr int PAD    = 36;               // smem row stride (floats): conflict-free frags
static constexpr int MAXT   = SLOTS/TM + NE;    // 136 worst-case M tiles

static constexpr int A_ELEM = TM * PAD;         // floats per A stage
static constexpr int B_ELEM = TN * PAD;         // floats per B stage
static constexpr int SMEM_TOTAL = (STAGES * (A_ELEM + B_ELEM)) * 4;   // 221184 B

// ---- device scratch (statics = sanctioned path; bss, not stored in cubin) ----
__device__ int   g_cnt[NE];
__device__ int   g_base[NE];
__device__ int   g_toff[NE + 1];
__device__ int   g_tok[NE][SLOTS];
__device__ float g_wt[NE][SLOTS];
__device__ float g_h  [(size_t)SLOTS * DFF];    // 268 MB, tf32-rounded activations
__device__ float g_xr [(size_t)T_TOK * DM];     // tf32-rounded x
__device__ float g_wir[(size_t)NE * DFF * DM];  // tf32-rounded wi
__device__ float g_wor[(size_t)NE * DM * DFF];  // tf32-rounded wo

// ---------------------------------------------------------------- helpers
__device__ __forceinline__ uint32_t smem_u32(const void* p) {
    uint32_t a;
    asm("{ .reg .u64 t; cvta.to.shared.u64 t, %1; cvt.u32.u64 %0, t; }" : "=r"(a) : "l"(p));
    return a;
}

__device__ __forceinline__ float rnd_tf32(float f) {
    uint32_t u;
    asm("cvt.rna.tf32.f32 %0, %1;" : "=r"(u) : "f"(f));
    return __uint_as_float(u);
}

__device__ __forceinline__ void mma_tf32(float c[4], const uint32_t a[4], const uint32_t b[2]) {
    asm volatile(
        "mma.sync.aligned.m16n8k8.row.col.f32.tf32.tf32.f32 "
        "{%0,%1,%2,%3}, {%4,%5,%6,%7}, {%8,%9}, {%0,%1,%2,%3};"
        : "+f"(c[0]), "+f"(c[1]), "+f"(c[2]), "+f"(c[3])
        : "r"(a[0]), "r"(a[1]), "r"(a[2]), "r"(a[3]), "r"(b[0]), "r"(b[1]));
}

__device__ __forceinline__ void cpa16(float* dst, const float* src, bool p) {
    uint32_t s = smem_u32(dst);
    int sz = p ? 16 : 0;
    asm volatile("cp.async.cg.shared.global [%0], [%1], 16, %2;\n" :: "r"(s), "l"(src), "r"(sz));
}

// ---------------------------------------------------------------- small kernels
__global__ void k_round(const float4* __restrict__ in, float4* __restrict__ out, int n4, int do_init) {
    if (do_init && blockIdx.x == 0 && threadIdx.x < NE) g_cnt[threadIdx.x] = 0;
    int i = blockIdx.x * blockDim.x + threadIdx.x;
    if (i < n4) {
        float4 v = in[i];
        v.x = rnd_tf32(v.x); v.y = rnd_tf32(v.y); v.z = rnd_tf32(v.z); v.w = rnd_tf32(v.w);
        out[i] = v;
    }
}

__global__ void k_zero(float4* p, int n4) {
    int i = blockIdx.x * blockDim.x + threadIdx.x;
    if (i < n4) p[i] = make_float4(0.f, 0.f, 0.f, 0.f);
}

__global__ void k_route(const int* __restrict__ sel, const float* __restrict__ rw) {
    int s = blockIdx.x * blockDim.x + threadIdx.x;
    if (s >= SLOTS) return;
    const int* v = sel + (size_t)s * NE;
    int e = 0;
    #pragma unroll
    for (int i = 1; i < NE; i++) if (v[i] != 0) e = i;
    int pos = atomicAdd(&g_cnt[e], 1);
    g_tok[e][pos] = s / TOPK;
    g_wt[e][pos]  = rw[s];
}

__global__ void k_sched() {
    int b = 0, t = 0;
    for (int e = 0; e < NE; e++) {
        g_base[e] = b; g_toff[e] = t;
        b += g_cnt[e];
        t += (g_cnt[e] + TM - 1) / TM;
    }
    g_toff[NE] = t;
}

// ---------------------------------------------------------------- grouped GEMM (legacy HMMA tf32)
// FIRST:  h[slot,n]  = rnd(relu( x[tok,:] . wi[e][n,:] ))    KD=DM,  Ntot=DFF
// !FIRST: out[tok,n] += w * ( h[slot,:] . wo[e][n,:] )       KD=DFF, Ntot=DM
template <bool FIRST, int KD>
__global__ __launch_bounds__(256, 1) void k_gemm(const float* __restrict__ Xin,
                                                 const float* __restrict__ Wm,
                                                 float* __restrict__ Oout)
{
    extern __shared__ float smem[];
    float* sA = smem;                         // [STAGES][A_ELEM]
    float* sB = smem + STAGES * A_ELEM;       // [STAGES][B_ELEM]

    constexpr int Ntot = FIRST ? DFF : DM;
    constexpr int NK   = KD / KC;

    int bx = blockIdx.x;
    int total = g_toff[NE];
    if (bx >= total) return;

    int e = 0;
    #pragma unroll
    for (int i = 1; i < NE; i++) if (bx >= g_toff[i]) e = i;
    int m0 = (bx - g_toff[e]) * TM, cnt = g_cnt[e], base = g_base[e];
    int n0 = blockIdx.y * TN;

    int tid  = threadIdx.x;
    int lane = tid & 31, w = tid >> 5;
    int g = lane >> 2, t4 = lane & 3;

    // ---- loaders. A: 2 thr/row x 64B (16 floats). B: 1 thr/row x 128B (32 floats).
    int rA = tid >> 1, cA = (tid & 1) * 16;
    int mrowA = m0 + rA;
    bool aok = mrowA < cnt;
    const float* aSrc;
    if (FIRST) {
        int tok = aok ? g_tok[e][mrowA] : 0;
        aSrc = Xin + (size_t)tok * KD;
    } else {
        aSrc = g_h + (size_t)(base + (aok ? mrowA : 0)) * KD;
    }
    const float* bSrc = Wm + ((size_t)e * Ntot + n0 + tid) * KD;

    auto load_stage = [&](int s) {
        int   b  = s % STAGES;
        float* ab = sA + b * A_ELEM + rA * PAD + cA;
        float* bb = sB + b * B_ELEM + tid * PAD;
        #pragma unroll
        for (int j = 0; j < 4; j++) cpa16(ab + j * 4, aSrc + s * KC + cA + j * 4, aok);
        #pragma unroll
        for (int j = 0; j < 8; j++) cpa16(bb + j * 4, bSrc + s * KC + j * 4, true);
    };

    #pragma unroll
    for (int s = 0; s < STAGES; s++) {
        load_stage(s);
        asm volatile("cp.async.commit_group;\n");
    }

    // ---- accumulators: warp tile 32 x 128 (warps 4 x 2)
    float acc[2][16][4];
    #pragma unroll
    for (int i = 0; i < 2; i++)
        #pragma unroll
        for (int j = 0; j < 16; j++)
            #pragma unroll
            for (int q = 0; q < 4; q++) acc[i][j][q] = 0.f;

    int wm0 = (w & 3) * 32, wn0 = (w >> 2) * 128;

    for (int s = 0; s < NK; s++) {
        int b = s % STAGES;
        asm volatile("cp.async.wait_group %0;\n" :: "n"(STAGES - 1));
        __syncthreads();

        const float* a0 = sA + b * A_ELEM;
        const float* b0p = sB + b * B_ELEM;

        #pragma unroll
        for (int kk = 0; kk < KC; kk += 8) {
            uint32_t af[2][4];
            #pragma unroll
            for (int ms = 0; ms < 2; ms++) {
                int r = wm0 + ms * 16;
                af[ms][0] = __float_as_uint(a0[(r + g    ) * PAD + kk + t4]);
                af[ms][1] = __float_as_uint(a0[(r + 8 + g) * PAD + kk + t4]);
                af[ms][2] = __float_as_uint(a0[(r + g    ) * PAD + kk + 4 + t4]);
                af[ms][3] = __float_as_uint(a0[(r + 8 + g) * PAD + kk + 4 + t4]);
            }
            uint32_t bf[16][2];
            #pragma unroll
            for (int ns = 0; ns < 16; ns++) {
                int c = wn0 + ns * 8;
                bf[ns][0] = __float_as_uint(b0p[(c + g) * PAD + kk + t4]);
                bf[ns][1] = __float_as_uint(b0p[(c + g) * PAD + kk + 4 + t4]);
            }
            #pragma unroll
            for (int ms = 0; ms < 2; ms++)
                #pragma unroll
                for (int ns = 0; ns < 16; ns++)
                    mma_tf32(acc[ms][ns], af[ms], bf[ns]);
        }
        __syncthreads();

        if (s + STAGES < NK) load_stage(s + STAGES);
        asm volatile("cp.async.commit_group;\n");
    }

    // ---- epilogue
    #pragma unroll
    for (int ms = 0; ms < 2; ms++) {
        int r0 = wm0 + ms * 16 + g;
        #pragma unroll
        for (int half = 0; half < 2; half++) {
            int lrow = r0 + half * 8;
            int mrow = m0 + lrow;
            if (mrow < cnt) {
                if (FIRST) {
                    float* hp = g_h + (size_t)(base + mrow) * DFF + n0 + wn0;
                    #pragma unroll
                    for (int ns = 0; ns < 16; ns++) {
                        float2 st;
                        st.x = rnd_tf32(fmaxf(acc[ms][ns][half * 2 + 0], 0.f));
                        st.y = rnd_tf32(fmaxf(acc[ms][ns][half * 2 + 1], 0.f));
                        *reinterpret_cast<float2*>(hp + ns * 8 + 2 * t4) = st;
                    }
                } else {
                    int   tok = g_tok[e][mrow];
                    float wgt = g_wt[e][mrow];
                    float* op = Oout + (size_t)tok * DM + n0 + wn0;
                    #pragma unroll
                    for (int ns = 0; ns < 16; ns++) {
                        atomicAdd(op + ns * 8 + 2 * t4,     wgt * acc[ms][ns][half * 2 + 0]);
                        atomicAdd(op + ns * 8 + 2 * t4 + 1, wgt * acc[ms][ns][half * 2 + 1]);
                    }
                }
            }
        }
    }
}

// ---------------------------------------------------------------- launch
extern "C" void kernel_launch(void* const* d_in, const int* in_sizes, int n_in,
                              void* d_out, int out_size)
{
    const float* x   = (const float*)d_in[0];   // [T, DM]
    const int*   sel = (const int*)  d_in[1];   // [T, K, E] one-hot int32
    const float* rw  = (const float*)d_in[2];   // [T, K]
    const float* wi  = (const float*)d_in[3];   // [E, DFF, DM]
    const float* wo  = (const float*)d_in[4];   // [E, DM, DFF]
    float* out = (float*)d_out;                 // [T, DM]

    float* xr;  cudaGetSymbolAddress((void**)&xr,  g_xr);
    float* wir; cudaGetSymbolAddress((void**)&wir, g_wir);
    float* wor; cudaGetSymbolAddress((void**)&wor, g_wor);

    cudaFuncSetAttribute(k_gemm<true,  DM >, cudaFuncAttributeMaxDynamicSharedMemorySize, SMEM_TOTAL);
    cudaFuncSetAttribute(k_gemm<false, DFF>, cudaFuncAttributeMaxDynamicSharedMemorySize, SMEM_TOTAL);

    int nx  = T_TOK * DM / 4;
    int nwi = NE * DFF * DM / 4;

    k_round<<<CDIV(nx, 256),  256>>>((const float4*)x,  (float4*)xr,  nx,  1);  // + g_cnt init
    k_round<<<CDIV(nwi, 256), 256>>>((const float4*)wi, (float4*)wir, nwi, 0);
    k_round<<<CDIV(nwi, 256), 256>>>((const float4*)wo, (float4*)wor, nwi, 0);
    k_route<<<CDIV(SLOTS, 256), 256>>>(sel, rw);
    k_sched<<<1, 1>>>();

    k_gemm<true, DM ><<<dim3(MAXT, DFF / TN), 256, SMEM_TOTAL>>>(xr, wir, nullptr);  // 6th launch (ncu -s 5)

    int n4 = out_size / 4;
    k_zero<<<CDIV(n4, 256), 256>>>((float4*)out, n4);

    k_gemm<false, DFF><<<dim3(MAXT, DM / TN), 256, SMEM_TOTAL>>>(nullptr, wor, out);
}

// round 4
// speedup vs baseline: 2.0521x; 2.0521x over previous
#include <cuda_runtime.h>
#include <cuda_fp16.h>
#include <cstdint>

#define CDIV(a,b) (((a)+(b)-1)/(b))

static constexpr int T_TOK = 8192;
static constexpr int DM    = 1024;
static constexpr int DFF   = 4096;
static constexpr int NE    = 8;
static constexpr int TOPK  = 2;
static constexpr int SLOTS = T_TOK * TOPK;      // 16384 routed slots

static constexpr int TM     = 128;
static constexpr int TN     = 128;
static constexpr int KC     = 64;               // K halfs per stage (128B row)
static constexpr int STAGES = 3;
static constexpr int PADH   = 72;               // halfs per smem row (144B stride)
static constexpr int PADB   = 144;
static constexpr int MAXT   = SLOTS/TM + NE;    // 136 worst-case M tiles

static constexpr int A_STAGE_B   = TM * PADB;            // 18432
static constexpr int STAGE_BYTES = (TM + TN) * PADB;     // 36864
static constexpr int SMEM_TOTAL  = STAGES * STAGE_BYTES; // 110592

// ---- device scratch (__device__ globals = sanctioned scratch path) ----
__device__ int    g_cnt[NE];
__device__ int    g_base[NE];
__device__ int    g_toff[NE + 1];
__device__ int    g_tok[NE][SLOTS];
__device__ float  g_wt[NE][SLOTS];
__device__ __half g_h  [(size_t)SLOTS * DFF];   // 134 MB fp16 activations
__device__ __half g_xh [(size_t)T_TOK * DM];    // fp16 x
__device__ __half g_wih[(size_t)NE * DFF * DM]; // fp16 wi
__device__ __half g_woh[(size_t)NE * DM * DFF]; // fp16 wo

// ---------------------------------------------------------------- helpers
__device__ __forceinline__ uint32_t smem_u32(const void* p) {
    uint32_t a;
    asm("{ .reg .u64 t; cvta.to.shared.u64 t, %1; cvt.u32.u64 %0, t; }" : "=r"(a) : "l"(p));
    return a;
}

__device__ __forceinline__ void ldsm_x4(uint32_t r[4], uint32_t addr) {
    asm volatile("ldmatrix.sync.aligned.m8n8.x4.shared.b16 {%0,%1,%2,%3}, [%4];"
        : "=r"(r[0]), "=r"(r[1]), "=r"(r[2]), "=r"(r[3]) : "r"(addr));
}

__device__ __forceinline__ void mma_fp16(float c[4], const uint32_t a[4], uint32_t b0, uint32_t b1) {
    asm volatile(
        "mma.sync.aligned.m16n8k16.row.col.f32.f16.f16.f32 "
        "{%0,%1,%2,%3}, {%4,%5,%6,%7}, {%8,%9}, {%0,%1,%2,%3};"
        : "+f"(c[0]), "+f"(c[1]), "+f"(c[2]), "+f"(c[3])
        : "r"(a[0]), "r"(a[1]), "r"(a[2]), "r"(a[3]), "r"(b0), "r"(b1));
}

__device__ __forceinline__ void cpa16(uint32_t dst, const void* src, bool p) {
    int sz = p ? 16 : 0;
    asm volatile("cp.async.cg.shared.global [%0], [%1], 16, %2;\n" :: "r"(dst), "l"(src), "r"(sz));
}

// ---------------------------------------------------------------- small kernels
__global__ void k_conv(const float4* __restrict__ in, __half2* __restrict__ out, int n4, int do_init) {
    if (do_init && blockIdx.x == 0 && threadIdx.x < NE) g_cnt[threadIdx.x] = 0;
    int i = blockIdx.x * blockDim.x + threadIdx.x;
    if (i < n4) {
        float4 v = in[i];
        out[2 * i]     = __floats2half2_rn(v.x, v.y);
        out[2 * i + 1] = __floats2half2_rn(v.z, v.w);
    }
}

__global__ void k_zero(float4* p, int n4) {
    int i = blockIdx.x * blockDim.x + threadIdx.x;
    if (i < n4) p[i] = make_float4(0.f, 0.f, 0.f, 0.f);
}

__global__ void k_route(const int* __restrict__ sel, const float* __restrict__ rw) {
    int s = blockIdx.x * blockDim.x + threadIdx.x;
    if (s >= SLOTS) return;
    const int* v = sel + (size_t)s * NE;
    int e = 0;
    #pragma unroll
    for (int i = 1; i < NE; i++) if (v[i] != 0) e = i;
    int pos = atomicAdd(&g_cnt[e], 1);
    g_tok[e][pos] = s / TOPK;
    g_wt[e][pos]  = rw[s];
}

__global__ void k_sched() {
    int b = 0, t = 0;
    for (int e = 0; e < NE; e++) {
        g_base[e] = b; g_toff[e] = t;
        b += g_cnt[e];
        t += (g_cnt[e] + TM - 1) / TM;
    }
    g_toff[NE] = t;
}

// ---------------------------------------------------------------- grouped fp16 GEMM
// FIRST:  h[slot,n]  = fp16(relu( x[tok,:] . wi[e][n,:] ))   KD=DM,  Ntot=DFF
// !FIRST: out[tok,n] += w * ( h[slot,:] . wo[e][n,:] )       KD=DFF, Ntot=DM
template <bool FIRST, int KD>
__global__ __launch_bounds__(256, 2) void k_gemm(const __half* __restrict__ Xin,
                                                 const __half* __restrict__ Wm,
                                                 float* __restrict__ Oout)
{
    extern __shared__ char smem[];
    constexpr int Ntot = FIRST ? DFF : DM;
    constexpr int NK   = KD / KC;

    int bx = blockIdx.x;
    int total = g_toff[NE];
    if (bx >= total) return;

    int e = 0;
    #pragma unroll
    for (int i = 1; i < NE; i++) if (bx >= g_toff[i]) e = i;
    int m0 = (bx - g_toff[e]) * TM, cnt = g_cnt[e], base = g_base[e];
    int n0 = blockIdx.y * TN;

    int tid  = threadIdx.x;
    int lane = tid & 31, w = tid >> 5;
    int g = lane >> 2, t4 = lane & 3;

    uint32_t sb = smem_u32(smem);

    // ---- loaders: 2 thr/row, each 64B (4 x 16B). A rows 0-127, B rows 128-255.
    int rA = tid >> 1;
    int co = (tid & 1) * 64;                        // byte offset within 128B row half
    int mrowA = m0 + rA;
    bool aok = mrowA < cnt;
    const __half* aSrc;
    if (FIRST) {
        int tok = aok ? g_tok[e][mrowA] : 0;
        aSrc = Xin + (size_t)tok * KD;
    } else {
        aSrc = g_h + (size_t)(base + (aok ? mrowA : 0)) * KD;
    }
    const __half* bSrc = Wm + ((size_t)e * Ntot + n0 + rA) * KD;

    uint32_t aDst = sb + rA * PADB + co;
    uint32_t bDst = sb + A_STAGE_B + rA * PADB + co;

    auto load_stage = [&](int s) {
        uint32_t st = (uint32_t)((s % STAGES) * STAGE_BYTES);
        const __half* ap = aSrc + s * KC + co / 2;
        const __half* bp = bSrc + s * KC + co / 2;
        #pragma unroll
        for (int j = 0; j < 4; j++) cpa16(aDst + st + j * 16, ap + j * 8, aok);
        #pragma unroll
        for (int j = 0; j < 4; j++) cpa16(bDst + st + j * 16, bp + j * 8, true);
    };

    #pragma unroll
    for (int s = 0; s < STAGES; s++) {
        load_stage(s);
        asm volatile("cp.async.commit_group;\n");
    }

    // ---- warp tile 32x64: warps (4 m) x (2 n)
    int wm0 = (w & 3) * 32, wn0 = (w >> 2) * 64;
    int lrow = lane & 15;
    int khiB = ((lane >> 4) << 3) * 2;              // 0 or 16 bytes (k-offset of 8 halfs)

    uint32_t aOff[2], bOff[4];
    #pragma unroll
    for (int ms = 0; ms < 2; ms++)
        aOff[ms] = sb + (uint32_t)((wm0 + ms * 16 + lrow) * PADB) + khiB;
    #pragma unroll
    for (int nb = 0; nb < 4; nb++)
        bOff[nb] = sb + A_STAGE_B + (uint32_t)((wn0 + nb * 16 + lrow) * PADB) + khiB;

    float acc[2][8][4];
    #pragma unroll
    for (int i = 0; i < 2; i++)
        #pragma unroll
        for (int j = 0; j < 8; j++)
            #pragma unroll
            for (int q = 0; q < 4; q++) acc[i][j][q] = 0.f;

    for (int s = 0; s < NK; s++) {
        uint32_t st = (uint32_t)((s % STAGES) * STAGE_BYTES);
        asm volatile("cp.async.wait_group %0;\n" :: "n"(STAGES - 1));
        __syncthreads();

        #pragma unroll
        for (int kk = 0; kk < KC; kk += 16) {
            uint32_t kb = (uint32_t)(kk * 2);
            uint32_t a[2][4];
            #pragma unroll
            for (int ms = 0; ms < 2; ms++) ldsm_x4(a[ms], aOff[ms] + st + kb);
            #pragma unroll
            for (int nb = 0; nb < 4; nb++) {
                uint32_t bq[4];
                ldsm_x4(bq, bOff[nb] + st + kb);
                #pragma unroll
                for (int ms = 0; ms < 2; ms++) {
                    mma_fp16(acc[ms][nb * 2],     a[ms], bq[0], bq[2]);
                    mma_fp16(acc[ms][nb * 2 + 1], a[ms], bq[1], bq[3]);
                }
            }
        }
        __syncthreads();

        if (s + STAGES < NK) load_stage(s + STAGES);
        asm volatile("cp.async.commit_group;\n");
    }

    // ---- epilogue
    #pragma unroll
    for (int ms = 0; ms < 2; ms++) {
        #pragma unroll
        for (int half = 0; half < 2; half++) {
            int lr   = wm0 + ms * 16 + half * 8 + g;
            int mrow = m0 + lr;
            if (mrow < cnt) {
                if (FIRST) {
                    __half* hp = g_h + (size_t)(base + mrow) * DFF + n0 + wn0;
                    #pragma unroll
                    for (int ns = 0; ns < 8; ns++) {
                        float v0 = fmaxf(acc[ms][ns][half * 2 + 0], 0.f);
                        float v1 = fmaxf(acc[ms][ns][half * 2 + 1], 0.f);
                        *reinterpret_cast<__half2*>(hp + ns * 8 + 2 * t4) = __floats2half2_rn(v0, v1);
                    }
                } else {
                    int   tok = g_tok[e][mrow];
                    float wgt = g_wt[e][mrow];
                    float* op = Oout + (size_t)tok * DM + n0 + wn0;
                    #pragma unroll
                    for (int ns = 0; ns < 8; ns++) {
                        atomicAdd(op + ns * 8 + 2 * t4,     wgt * acc[ms][ns][half * 2 + 0]);
                        atomicAdd(op + ns * 8 + 2 * t4 + 1, wgt * acc[ms][ns][half * 2 + 1]);
                    }
                }
            }
        }
    }
}

// ---------------------------------------------------------------- launch
extern "C" void kernel_launch(void* const* d_in, const int* in_sizes, int n_in,
                              void* d_out, int out_size)
{
    const float* x   = (const float*)d_in[0];   // [T, DM]
    const int*   sel = (const int*)  d_in[1];   // [T, K, E] one-hot int32
    const float* rw  = (const float*)d_in[2];   // [T, K]
    const float* wi  = (const float*)d_in[3];   // [E, DFF, DM]
    const float* wo  = (const float*)d_in[4];   // [E, DM, DFF]
    float* out = (float*)d_out;                 // [T, DM]

    __half* xh;  cudaGetSymbolAddress((void**)&xh,  g_xh);
    __half* wih; cudaGetSymbolAddress((void**)&wih, g_wih);
    __half* woh; cudaGetSymbolAddress((void**)&woh, g_woh);

    cudaFuncSetAttribute(k_gemm<true,  DM >, cudaFuncAttributeMaxDynamicSharedMemorySize, SMEM_TOTAL);
    cudaFuncSetAttribute(k_gemm<false, DFF>, cudaFuncAttributeMaxDynamicSharedMemorySize, SMEM_TOTAL);

    int nx  = T_TOK * DM / 4;
    int nwi = NE * DFF * DM / 4;

    k_conv<<<CDIV(nx, 256),  256>>>((const float4*)x,  (__half2*)xh,  nx,  1);  // + g_cnt init
    k_conv<<<CDIV(nwi, 256), 256>>>((const float4*)wi, (__half2*)wih, nwi, 0);
    k_conv<<<CDIV(nwi, 256), 256>>>((const float4*)wo, (__half2*)woh, nwi, 0);
    k_route<<<CDIV(SLOTS, 256), 256>>>(sel, rw);
    k_sched<<<1, 1>>>();

    k_gemm<true, DM ><<<dim3(MAXT, DFF / TN), 256, SMEM_TOTAL>>>(xh, wih, nullptr);  // 6th launch (ncu -s 5)

    int n4 = out_size / 4;
    k_zero<<<CDIV(n4, 256), 256>>>((float4*)out, n4);

    k_gemm<false, DFF><<<dim3(MAXT, DM / TN), 256, SMEM_TOTAL>>>(nullptr, woh, out);
}

// round 5
// speedup vs baseline: 2.0676x; 1.0076x over previous
#include <cuda_runtime.h>
#include <cuda_fp16.h>
#include <cstdint>

#define CDIV(a,b) (((a)+(b)-1)/(b))

static constexpr int T_TOK = 8192;
static constexpr int DM    = 1024;
static constexpr int DFF   = 4096;
static constexpr int NE    = 8;
static constexpr int TOPK  = 2;
static constexpr int SLOTS = T_TOK * TOPK;      // 16384 routed slots

static constexpr int TM     = 128;
static constexpr int TN     = 128;
static constexpr int KC     = 64;               // K halfs per stage (128B row)
static constexpr int STAGES = 3;
static constexpr int PADB   = 144;              // bytes per smem row (conflict-free ldmatrix)
static constexpr int MAXT   = SLOTS/TM + NE;    // 136 worst-case M tiles

static constexpr int A_STAGE_B   = TM * PADB;            // 18432
static constexpr int STAGE_BYTES = (TM + TN) * PADB;     // 36864
static constexpr int SMEM_TOTAL  = STAGES * STAGE_BYTES; // 110592 (2 CTA/SM)

// ---- device scratch (__device__ globals = sanctioned scratch path) ----
__device__ int    g_cnt[NE];
__device__ int    g_base[NE];
__device__ int    g_toff[NE + 1];
__device__ int    g_tok[NE][SLOTS];
__device__ float  g_wt[NE][SLOTS];
__device__ __half g_h  [(size_t)SLOTS * DFF];   // 134 MB fp16 activations
__device__ __half g_xh [(size_t)T_TOK * DM];    // fp16 x
__device__ __half g_wih[(size_t)NE * DFF * DM]; // fp16 wi
__device__ __half g_woh[(size_t)NE * DM * DFF]; // fp16 wo

// ---------------------------------------------------------------- helpers
__device__ __forceinline__ uint32_t smem_u32(const void* p) {
    uint32_t a;
    asm("{ .reg .u64 t; cvta.to.shared.u64 t, %1; cvt.u32.u64 %0, t; }" : "=r"(a) : "l"(p));
    return a;
}

__device__ __forceinline__ void ldsm_x4(uint32_t r[4], uint32_t addr) {
    asm volatile("ldmatrix.sync.aligned.m8n8.x4.shared.b16 {%0,%1,%2,%3}, [%4];"
        : "=r"(r[0]), "=r"(r[1]), "=r"(r[2]), "=r"(r[3]) : "r"(addr));
}

__device__ __forceinline__ void mma_fp16(float c[4], const uint32_t a[4], uint32_t b0, uint32_t b1) {
    asm volatile(
        "mma.sync.aligned.m16n8k16.row.col.f32.f16.f16.f32 "
        "{%0,%1,%2,%3}, {%4,%5,%6,%7}, {%8,%9}, {%0,%1,%2,%3};"
        : "+f"(c[0]), "+f"(c[1]), "+f"(c[2]), "+f"(c[3])
        : "r"(a[0]), "r"(a[1]), "r"(a[2]), "r"(a[3]), "r"(b0), "r"(b1));
}

__device__ __forceinline__ void cpa16(uint32_t dst, const void* src, bool p) {
    int sz = p ? 16 : 0;
    asm volatile("cp.async.cg.shared.global [%0], [%1], 16, %2;\n" :: "r"(dst), "l"(src), "r"(sz));
}

// ---------------------------------------------------------------- small kernels
__global__ void k_zero(float4* p, int n4) {
    if (blockIdx.x == 0 && threadIdx.x < NE) g_cnt[threadIdx.x] = 0;
    int i = blockIdx.x * blockDim.x + threadIdx.x;
    if (i < n4) p[i] = make_float4(0.f, 0.f, 0.f, 0.f);
}

// one launch converts x, wi, wo -> fp16
__global__ void k_conv3(const float4* __restrict__ x,  __half2* __restrict__ xh,  int nx,
                        const float4* __restrict__ wi, __half2* __restrict__ wih,
                        const float4* __restrict__ wo, __half2* __restrict__ woh, int nw)
{
    int i = blockIdx.x * blockDim.x + threadIdx.x;
    const float4* src; __half2* dst; int j;
    if (i < nx)              { src = x;  dst = xh;  j = i; }
    else if (i < nx + nw)    { src = wi; dst = wih; j = i - nx; }
    else if (i < nx + 2*nw)  { src = wo; dst = woh; j = i - nx - nw; }
    else return;
    float4 v = src[j];
    dst[2 * j]     = __floats2half2_rn(v.x, v.y);
    dst[2 * j + 1] = __floats2half2_rn(v.z, v.w);
}

__global__ void k_route(const int* __restrict__ sel, const float* __restrict__ rw) {
    int s = blockIdx.x * blockDim.x + threadIdx.x;
    if (s >= SLOTS) return;
    const int* v = sel + (size_t)s * NE;
    int e = 0;
    #pragma unroll
    for (int i = 1; i < NE; i++) if (v[i] != 0) e = i;
    int pos = atomicAdd(&g_cnt[e], 1);
    g_tok[e][pos] = s / TOPK;
    g_wt[e][pos]  = rw[s];
}

__global__ void k_sched() {
    int b = 0, t = 0;
    for (int e = 0; e < NE; e++) {
        g_base[e] = b; g_toff[e] = t;
        b += g_cnt[e];
        t += (g_cnt[e] + TM - 1) / TM;
    }
    g_toff[NE] = t;
}

// ---------------------------------------------------------------- grouped fp16 GEMM
// FIRST:  h[slot,n]  = fp16(relu( x[tok,:] . wi[e][n,:] ))   KD=DM,  Ntot=DFF
// !FIRST: out[tok,n] += w * ( h[slot,:] . wo[e][n,:] )       KD=DFF, Ntot=DM
template <bool FIRST, int KD>
__global__ __launch_bounds__(256, 2) void k_gemm(const __half* __restrict__ Xin,
                                                 const __half* __restrict__ Wm,
                                                 float* __restrict__ Oout)
{
    extern __shared__ char smem[];
    constexpr int Ntot = FIRST ? DFF : DM;
    constexpr int NK   = KD / KC;

    int bx = blockIdx.x;
    int total = g_toff[NE];
    if (bx >= total) return;

    int e = 0;
    #pragma unroll
    for (int i = 1; i < NE; i++) if (bx >= g_toff[i]) e = i;
    int m0 = (bx - g_toff[e]) * TM, cnt = g_cnt[e], base = g_base[e];
    int n0 = blockIdx.y * TN;

    int tid  = threadIdx.x;
    int lane = tid & 31, w = tid >> 5;
    int g = lane >> 2, t4 = lane & 3;

    uint32_t sb = smem_u32(smem);

    // ---- loaders: 2 thr/row, each 64B (4 x 16B). A rows 0-127, B rows 128-255.
    int rA = tid >> 1;
    int co = (tid & 1) * 64;                        // byte offset within 128B row
    int mrowA = m0 + rA;
    bool aok = mrowA < cnt;
    const __half* aSrc;
    if (FIRST) {
        int tok = aok ? g_tok[e][mrowA] : 0;
        aSrc = Xin + (size_t)tok * KD;
    } else {
        aSrc = g_h + (size_t)(base + (aok ? mrowA : 0)) * KD;
    }
    const __half* bSrc = Wm + ((size_t)e * Ntot + n0 + rA) * KD;

    uint32_t aDst = sb + rA * PADB + co;
    uint32_t bDst = sb + A_STAGE_B + rA * PADB + co;

    auto load_stage = [&](int s) {
        uint32_t st = (uint32_t)((s % STAGES) * STAGE_BYTES);
        const __half* ap = aSrc + s * KC + co / 2;
        const __half* bp = bSrc + s * KC + co / 2;
        #pragma unroll
        for (int j = 0; j < 4; j++) cpa16(aDst + st + j * 16, ap + j * 8, aok);
        #pragma unroll
        for (int j = 0; j < 4; j++) cpa16(bDst + st + j * 16, bp + j * 8, true);
    };

    // prologue: STAGES-1 stages in flight
    #pragma unroll
    for (int s = 0; s < STAGES - 1; s++) {
        load_stage(s);
        asm volatile("cp.async.commit_group;\n");
    }

    // ---- warp tile 32x64: warps (4 m) x (2 n)
    int wm0 = (w & 3) * 32, wn0 = (w >> 2) * 64;
    int lrow = lane & 15;
    int khiB = ((lane >> 4) << 3) * 2;              // 0 or 16B (k-offset of 8 halfs)

    uint32_t aOff[2], bOff[4];
    #pragma unroll
    for (int ms = 0; ms < 2; ms++)
        aOff[ms] = sb + (uint32_t)((wm0 + ms * 16 + lrow) * PADB) + khiB;
    #pragma unroll
    for (int nb = 0; nb < 4; nb++)
        bOff[nb] = sb + A_STAGE_B + (uint32_t)((wn0 + nb * 16 + lrow) * PADB) + khiB;

    float acc[2][8][4];
    #pragma unroll
    for (int i = 0; i < 2; i++)
        #pragma unroll
        for (int j = 0; j < 8; j++)
            #pragma unroll
            for (int q = 0; q < 4; q++) acc[i][j][q] = 0.f;

    for (int s = 0; s < NK; s++) {
        asm volatile("cp.async.wait_group %0;\n" :: "n"(STAGES - 2));
        __syncthreads();

        // issue next loads FIRST (buffer (s+2)%3 — its readers finished before the sync above)
        if (s + STAGES - 1 < NK) load_stage(s + STAGES - 1);
        asm volatile("cp.async.commit_group;\n");

        uint32_t st = (uint32_t)((s % STAGES) * STAGE_BYTES);
        #pragma unroll
        for (int kk = 0; kk < KC; kk += 16) {
            uint32_t kb = (uint32_t)(kk * 2);
            uint32_t a[2][4];
            #pragma unroll
            for (int ms = 0; ms < 2; ms++) ldsm_x4(a[ms], aOff[ms] + st + kb);
            #pragma unroll
            for (int nb = 0; nb < 4; nb++) {
                uint32_t bq[4];
                ldsm_x4(bq, bOff[nb] + st + kb);
                #pragma unroll
                for (int ms = 0; ms < 2; ms++) {
                    mma_fp16(acc[ms][nb * 2],     a[ms], bq[0], bq[2]);
                    mma_fp16(acc[ms][nb * 2 + 1], a[ms], bq[1], bq[3]);
                }
            }
        }
    }

    // ---- epilogue
    #pragma unroll
    for (int ms = 0; ms < 2; ms++) {
        #pragma unroll
        for (int half = 0; half < 2; half++) {
            int lr   = wm0 + ms * 16 + half * 8 + g;
            int mrow = m0 + lr;
            if (mrow < cnt) {
                if (FIRST) {
                    __half* hp = g_h + (size_t)(base + mrow) * DFF + n0 + wn0;
                    #pragma unroll
                    for (int ns = 0; ns < 8; ns++) {
                        float v0 = fmaxf(acc[ms][ns][half * 2 + 0], 0.f);
                        float v1 = fmaxf(acc[ms][ns][half * 2 + 1], 0.f);
                        *reinterpret_cast<__half2*>(hp + ns * 8 + 2 * t4) = __floats2half2_rn(v0, v1);
                    }
                } else {
                    int   tok = g_tok[e][mrow];
                    float wgt = g_wt[e][mrow];
                    float* op = Oout + (size_t)tok * DM + n0 + wn0;
                    #pragma unroll
                    for (int ns = 0; ns < 8; ns++) {
                        atomicAdd(op + ns * 8 + 2 * t4,     wgt * acc[ms][ns][half * 2 + 0]);
                        atomicAdd(op + ns * 8 + 2 * t4 + 1, wgt * acc[ms][ns][half * 2 + 1]);
                    }
                }
            }
        }
    }
}

// ---------------------------------------------------------------- launch
extern "C" void kernel_launch(void* const* d_in, const int* in_sizes, int n_in,
                              void* d_out, int out_size)
{
    const float* x   = (const float*)d_in[0];   // [T, DM]
    const int*   sel = (const int*)  d_in[1];   // [T, K, E] one-hot int32
    const float* rw  = (const float*)d_in[2];   // [T, K]
    const float* wi  = (const float*)d_in[3];   // [E, DFF, DM]
    const float* wo  = (const float*)d_in[4];   // [E, DM, DFF]
    float* out = (float*)d_out;                 // [T, DM]

    __half* xh;  cudaGetSymbolAddress((void**)&xh,  g_xh);
    __half* wih; cudaGetSymbolAddress((void**)&wih, g_wih);
    __half* woh; cudaGetSymbolAddress((void**)&woh, g_woh);

    cudaFuncSetAttribute(k_gemm<true,  DM >, cudaFuncAttributeMaxDynamicSharedMemorySize, SMEM_TOTAL);
    cudaFuncSetAttribute(k_gemm<false, DFF>, cudaFuncAttributeMaxDynamicSharedMemorySize, SMEM_TOTAL);

    int nx  = T_TOK * DM / 4;
    int nw  = NE * DFF * DM / 4;
    int n4  = out_size / 4;

    k_zero <<<CDIV(n4, 256), 256>>>((float4*)out, n4);                       // 1 (+cnt init)
    k_conv3<<<CDIV(nx + 2 * nw, 256), 256>>>((const float4*)x,  (__half2*)xh,  nx,
                                             (const float4*)wi, (__half2*)wih,
                                             (const float4*)wo, (__half2*)woh, nw);  // 2
    k_route<<<CDIV(SLOTS, 256), 256>>>(sel, rw);                             // 3
    k_sched<<<1, 1>>>();                                                     // 4

    k_gemm<true, DM ><<<dim3(MAXT, DFF / TN), 256, SMEM_TOTAL>>>(xh, wih, nullptr);  // 5
    k_gemm<false, DFF><<<dim3(MAXT, DM / TN), 256, SMEM_TOTAL>>>(nullptr, woh, out); // 6 (ncu -s 5)
}